// round 13
// baseline (speedup 1.0000x reference)
#include <cuda_runtime.h>

#define BB   256
#define TT   1024
#define SS   7
#define HH   64
#define LL   4
#define OO   3
#define UU   4
#define BETA 0.8f
#define TH   1.0f
#define NEPOCH (TT / UU)      // 256
#define ROWF   68             // padded spike row: half0 at byte 0, half1 at byte 144

typedef unsigned long long u64;

// Packed f32x2 FMA: one issue, two fp32 FMAs (PTX-only on Blackwell).
__device__ __forceinline__ u64 ffma2(u64 a, u64 b, u64 c) {
    u64 d;
    asm("fma.rn.f32x2 %0, %1, %2, %3;" : "=l"(d) : "l"(a), "l"(b), "l"(c));
    return d;
}
__device__ __forceinline__ float2 unpack2(u64 v) {
    float2 f;
    asm("mov.b64 {%0, %1}, %2;" : "=f"(f.x), "=f"(f.y) : "l"(v));
    return f;
}

// 32-element dot product: spike chunk (16B-aligned SMEM) x packed weight row.
// 8 ulonglong2 loads x 16B = 128B = all 32 floats (R11 bug: ran only 4 iters
// = 16 floats). 16 FFMA2 + 8 LDS.128 per call; consumes wp[0..15] fully.
__device__ __forceinline__ float dot32p(const float* __restrict__ sp,
                                        const u64* __restrict__ wp) {
    const ulonglong2* sp2 = (const ulonglong2*)sp;
    u64 acc0 = 0ull, acc1 = 0ull;
    #pragma unroll
    for (int i = 0; i < 8; i++) {
        ulonglong2 sv = sp2[i];
        acc0 = ffma2(sv.x, wp[2 * i + 0], acc0);
        acc1 = ffma2(sv.y, wp[2 * i + 1], acc1);
    }
    float2 f0 = unpack2(acc0), f1 = unpack2(acc1);
    return (f0.x + f0.y) + (f1.x + f1.y);
}

// One CTA per batch element, 544 threads, 2 CTAs/SM (34 warps).
// tids 0..511: layer threads. l = tid>>7, q = tid&127, unit h = q>>1, half = q&1.
// Each thread holds HALF a weight row packed as 16 f32x2 regs, computes a
// 32-MAC partial in 16 FFMA2, combines with its lane-pair via shfl_xor(1).
// Both halves run the membrane chain redundantly; only half==0 stores.
// tids 512..517: output layer (3 outputs x 2 halves).
// Pipeline over epochs of UU=4 timesteps, double-buffered spikes, one
// __syncthreads per epoch. Identical structure to the 352.8us R9 kernel;
// only the dot-product instruction form changed.
__global__ __launch_bounds__(544, 2)
void snn_split2_kernel(const float* __restrict__ x,
                       const float* __restrict__ hidden0,
                       const float* __restrict__ w1,
                       const float* __restrict__ b1,
                       const float* __restrict__ w_h,
                       const float* __restrict__ b_h,
                       const float* __restrict__ w_out,
                       const float* __restrict__ b_out,
                       float* __restrict__ out_outputs,   // [B,T,OO]
                       float* __restrict__ out_hidden,    // [B,T,LL,HH]
                       float* __restrict__ out_xcopy)     // [B,T,SS]
{
    const int b   = blockIdx.x;
    const int tid = threadIdx.x;

    __shared__ __align__(16) float spk[2][LL][UU][ROWF];

    // ---- copy this batch's x slice to the output buffer (coalesced float4) ----
    {
        const float4* xs4 = (const float4*)(x + (size_t)b * TT * SS);
        float4*       xo4 = (float4*)(out_xcopy + (size_t)b * TT * SS);
        const int n4 = TT * SS / 4;  // 1792
        for (int i = tid; i < n4; i += blockDim.x) xo4[i] = xs4[i];
    }

    const bool is_layer = (tid < LL * HH * 2);           // 512
    const bool is_out   = (tid >= 512) && (tid < 512 + 2 * OO);
    const int  l    = tid >> 7;
    const int  q    = tid & 127;
    const int  h    = q >> 1;
    const int  half = q & 1;

    u64   wp[16];            // packed half weight row (l>0 / out)
    float w0[4];             // layer-0 partial row
    float bias = 0.0f;
    float m    = 0.0f;
    int   hoff = 0;

    if (is_layer) {
        m    = hidden0[(size_t)b * TT * LL * HH + (size_t)l * HH + h];
        hoff = h + ((h >= 32) ? 4 : 0);
        if (l == 0) {
            bias = b1[h];
            w0[0] = w1[h * SS + half * 4 + 0];
            w0[1] = w1[h * SS + half * 4 + 1];
            w0[2] = w1[h * SS + half * 4 + 2];
            w0[3] = half ? 0.0f : w1[h * SS + 3];
        } else {
            const u64* row = (const u64*)(w_h + ((size_t)(l - 1) * HH + h) * HH + half * 32);
            #pragma unroll
            for (int i = 0; i < 16; i++) wp[i] = row[i];
            bias = b_h[(l - 1) * HH + h];
        }
    } else if (is_out) {
        const int oj = (tid - 512) >> 1;
        const int oh = (tid - 512) & 1;
        const u64* row = (const u64*)(w_out + (size_t)oj * HH + oh * 32);
        #pragma unroll
        for (int i = 0; i < 16; i++) wp[i] = row[i];
        bias = b_out[oj];
    }

    __syncthreads();

    const float* xrow   = x + (size_t)b * TT * SS;
    float*       hidptr = out_hidden + (size_t)b * TT * LL * HH
                          + (is_layer ? (l * HH + h) : 0);
    float*       outptr = out_outputs + (size_t)b * TT * OO
                          + (is_out ? ((tid - 512) >> 1) : 0);

    int buf = 0;
    for (int e = 0; e < NEPOCH + LL; e++) {
        if (is_layer) {
            if (e >= l && e < l + NEPOCH) {
                float p[UU];
                if (l == 0) {
                    #pragma unroll
                    for (int k = 0; k < UU; k++) {
                        const float* xr = xrow + k * SS + half * 4;
                        float a = 0.f;
                        a = fmaf(xr[0], w0[0], a);
                        a = fmaf(xr[1], w0[1], a);
                        a = fmaf(xr[2], w0[2], a);
                        if (!half) a = fmaf(xr[3], w0[3], a);
                        p[k] = a;
                    }
                    xrow += UU * SS;
                } else {
                    #pragma unroll
                    for (int k = 0; k < UU; k++)
                        p[k] = dot32p(&spk[buf ^ 1][l - 1][k][half * 36], wp);
                }
                #pragma unroll
                for (int k = 0; k < UU; k++) {
                    const float tot = p[k] + __shfl_xor_sync(0xffffffffu, p[k], 1);
                    const float c   = bias + tot;
                    const float reset = (m > TH) ? TH : 0.0f;
                    const float m_new = fmaf(BETA, m, c) - reset;
                    m = m_new;
                    if (!half) {
                        spk[buf][l][k][hoff] = (m_new > TH) ? 1.0f : 0.0f;
                        hidptr[(size_t)k * (LL * HH)] = m_new;
                    }
                }
                hidptr += (size_t)UU * LL * HH;
            }
        } else if (is_out) {
            if (e >= LL) {
                const int oh = (tid - 512) & 1;
                #pragma unroll
                for (int k = 0; k < UU; k++) {
                    float pk  = dot32p(&spk[buf ^ 1][LL - 1][k][oh * 36], wp);
                    float tot = pk + __shfl_xor_sync(0x3fu, pk, 1);
                    if (!oh) outptr[k * OO] = bias + tot;
                }
                outptr += UU * OO;
            }
        }
        __syncthreads();
        buf ^= 1;
    }
}

extern "C" void kernel_launch(void* const* d_in, const int* in_sizes, int n_in,
                              void* d_out, int out_size) {
    // metadata order: x, hidden_states, prev_obs, w1, b1, w_h, b_h, w_out, b_out
    const float* x       = (const float*)d_in[0];
    const float* hidden0 = (const float*)d_in[1];
    // d_in[2] = prev_obs (unused by reference)
    const float* w1      = (const float*)d_in[3];
    const float* b1      = (const float*)d_in[4];
    const float* w_h     = (const float*)d_in[5];
    const float* b_h     = (const float*)d_in[6];
    const float* w_out   = (const float*)d_in[7];
    const float* b_out   = (const float*)d_in[8];

    float* out_outputs = (float*)d_out;                                  // B*T*OO
    float* out_hidden  = out_outputs + (size_t)BB * TT * OO;             // B*T*LL*HH
    float* out_xcopy   = out_hidden + (size_t)BB * TT * LL * HH;         // B*T*SS

    snn_split2_kernel<<<BB, 544>>>(x, hidden0, w1, b1, w_h, b_h, w_out, b_out,
                                   out_outputs, out_hidden, out_xcopy);
}